// round 6
// baseline (speedup 1.0000x reference)
#include <cuda_runtime.h>

#define ND 600
#define NPRO 19081
#define NSE 964
#define EMB 128
#define FEAT 2048
#define NE 1200000
#define NPAIRS 8192
#define NANCH 8192
#define NV 19681
#define KSPLIT 32
#define MPAD 640
#define BCAP 160

// phase-1 block-role partition (all 256-thread blocks)
#define EDGE_BLKS 516
#define MLP1_BLKS 608          /* 19 row-tiles x 32 k-splits */
#define INIT_BLKS 320          /* 81920 transpose elements / 256 */
#define P1_GRID (EDGE_BLKS + MLP1_BLKS + INIT_BLKS)

// ---------------- scratch (static device globals; zero-initialized at load) -----
__device__ float g_part[KSPLIT * MPAD * EMB];   // mlp1 split-K partials
__device__ float g_xd[ND * EMB];                // relu MLP output == xF[:600]
__device__ float g_U[ND * EMB];                 // x600 @ Wa^T
__device__ float g_V[ND * EMB];                 // x600 @ Wb^T
__device__ int   g_deg[ND];                     // degree == bucket cursor (zeroed by k_final tail)
__device__ int   g_bkt[ND * BCAP];              // per-node src buckets
__device__ float g_W2t[EMB * EMB];              // W2^T        [k][o]
__device__ float g_Wlt[EMB * EMB];              // sageWl[1]^T [k][o]
__device__ float g_Wrt[EMB * EMB];              // sageWr[1]^T [k][o]
__device__ float g_W1pt[2 * EMB * EMB];         // outW1^T     [k(0..255)][o]

// ================= phase 1: edges scatter + MLP1 split-K GEMM + weight transposes
__global__ void k_phase1(const int* __restrict__ ei,
                         const float* __restrict__ A, const float* __restrict__ W,
                         const float* __restrict__ W2, const float* __restrict__ Wl,
                         const float* __restrict__ Wr, const float* __restrict__ oW1) {
    __shared__ __align__(16) float As[16][32];
    __shared__ __align__(16) float Bs[16][128];
    int b = blockIdx.x;
    int t = threadIdx.x;

    if (b < EDGE_BLKS) {
        const int4* dst4 = (const int4*)(ei + NE);
        int stride = EDGE_BLKS * 256;
        for (int i = b * 256 + t; i < NE / 4; i += stride) {
            int4 d4 = dst4[i];
            int base = i * 4;
            if (d4.x < ND) { int p = atomicAdd(&g_deg[d4.x], 1); g_bkt[d4.x * BCAP + p] = ei[base + 0]; }
            if (d4.y < ND) { int p = atomicAdd(&g_deg[d4.y], 1); g_bkt[d4.y * BCAP + p] = ei[base + 1]; }
            if (d4.z < ND) { int p = atomicAdd(&g_deg[d4.z], 1); g_bkt[d4.z * BCAP + p] = ei[base + 2]; }
            if (d4.w < ND) { int p = atomicAdd(&g_deg[d4.w], 1); g_bkt[d4.w * BCAP + p] = ei[base + 3]; }
        }
        return;
    }
    if (b < EDGE_BLKS + MLP1_BLKS) {
        int b2 = b - EDGE_BLKS;
        int rt = b2 % 19, ks = b2 / 19;
        int tx = t & 31, ty = t >> 5;
        int rowBase = rt * 32;
        int kbase = ks * 64;
        float acc[4][4];
#pragma unroll
        for (int i = 0; i < 4; i++)
#pragma unroll
            for (int j = 0; j < 4; j++) acc[i][j] = 0.f;

        for (int kk = 0; kk < 4; kk++) {
            if (t < 128) {
                int r = t >> 2, c4 = t & 3;
                int row = rowBase + r;
                float4 va = make_float4(0.f, 0.f, 0.f, 0.f);
                if (row < ND) va = *(const float4*)(A + row * FEAT + kbase + kk * 16 + c4 * 4);
                As[c4 * 4 + 0][r] = va.x; As[c4 * 4 + 1][r] = va.y;
                As[c4 * 4 + 2][r] = va.z; As[c4 * 4 + 3][r] = va.w;
            }
#pragma unroll
            for (int q = 0; q < 2; q++) {
                int idx = t + q * 256;
                int wr = idx >> 2, wc = idx & 3;
                float4 vb = *(const float4*)(W + wr * FEAT + kbase + kk * 16 + wc * 4);
                Bs[wc * 4 + 0][wr] = vb.x; Bs[wc * 4 + 1][wr] = vb.y;
                Bs[wc * 4 + 2][wr] = vb.z; Bs[wc * 4 + 3][wr] = vb.w;
            }
            __syncthreads();
#pragma unroll
            for (int k = 0; k < 16; k++) {
                float a[4], bb[4];
                *(float4*)(a)  = *(const float4*)&As[k][ty * 4];
                *(float4*)(bb) = *(const float4*)&Bs[k][tx * 4];
#pragma unroll
                for (int i = 0; i < 4; i++)
#pragma unroll
                    for (int j = 0; j < 4; j++) acc[i][j] += a[i] * bb[j];
            }
            __syncthreads();
        }
        float* out = g_part + ks * (MPAD * EMB) + rowBase * EMB;
#pragma unroll
        for (int i = 0; i < 4; i++) {
            float4 v = make_float4(acc[i][0], acc[i][1], acc[i][2], acc[i][3]);
            *(float4*)(out + (ty * 4 + i) * EMB + tx * 4) = v;
        }
        return;
    }
    int idx = (b - EDGE_BLKS - MLP1_BLKS) * 256 + t;       // [0, 81920)
    if (idx < 16384) {
        int k = idx >> 7, o = idx & 127;
        g_W2t[idx] = W2[o * 128 + k];
    } else if (idx < 32768) {
        int f = idx - 16384; int k = f >> 7, o = f & 127;
        g_Wlt[f] = Wl[o * 128 + k];
    } else if (idx < 49152) {
        int f = idx - 32768; int k = f >> 7, o = f & 127;
        g_Wrt[f] = Wr[o * 128 + k];
    } else {
        int f = idx - 49152; int k = f >> 7, o = f & 127;   // k in [0,256)
        g_W1pt[f] = oW1[o * 256 + k];
    }
}

// ================= phase 2: split-K reduce + bias + relu + MLP2 (600 x 512) ======
__global__ void k_mlp12(const float* __restrict__ b1, const float* __restrict__ b2) {
    int row = blockIdx.x;
    int t = threadIdx.x;            // 512
    int col = t & 127, q = t >> 7;  // q in [0,4)
    __shared__ float red[512];
    __shared__ float hs[128];
    float s = 0.f;
    const float* p = g_part + row * EMB + col;
#pragma unroll
    for (int i = 0; i < 8; i++) s += p[(q * 8 + i) * (MPAD * EMB)];
    red[t] = s;
    __syncthreads();
    if (t < 128) {
        float h = red[t] + red[t + 128] + red[t + 256] + red[t + 384] + b1[t];
        hs[t] = fmaxf(h, 0.f);
    }
    __syncthreads();
    float a0 = 0.f, a1 = 0.f;
#pragma unroll
    for (int k = 0; k < 32; k += 2) {
        int kk = q * 32 + k;
        a0 += hs[kk] * g_W2t[kk * 128 + col];
        a1 += hs[kk + 1] * g_W2t[(kk + 1) * 128 + col];
    }
    red[t] = a0 + a1;
    __syncthreads();
    if (t < 128) {
        float r = red[t] + red[t + 128] + red[t + 256] + red[t + 384] + b2[t];
        g_xd[row * EMB + t] = fmaxf(r, 0.f);
    }
}

// ================= phase 3: aggregation + SAGE + U/V (600 x 512, 4-way split) ====
__device__ __forceinline__ const float* node_row(int s, const float* protEmb) {
    return (s < ND) ? g_xd + s * EMB : protEmb + (s - ND) * EMB;
}

__global__ void k_aggsage(const float* __restrict__ protEmb, const float* __restrict__ bl) {
    int v = blockIdx.x;
    int t = threadIdx.x;            // 512
    int col = t & 127, q = t >> 7;  // q in [0,4)
    __shared__ float redA[512], redB[512];
    __shared__ float s1[128], s2[128], sx[128];
    __shared__ int sidx[BCAP];
    int deg = g_deg[v];
    if (t < deg) sidx[t] = g_bkt[v * BCAP + t];     // deg <= BCAP < 512
    __syncthreads();
    // group q sums neighbors j = q, q+4, q+8, ... (coalesced 512B row reads)
    float sum = 0.f;
    int j = q;
    for (; j + 12 < deg; j += 16) {
        const float* p0 = node_row(sidx[j],      protEmb);
        const float* p1 = node_row(sidx[j + 4],  protEmb);
        const float* p2 = node_row(sidx[j + 8],  protEmb);
        const float* p3 = node_row(sidx[j + 12], protEmb);
        sum += (p0[col] + p1[col]) + (p2[col] + p3[col]);
    }
    for (; j < deg; j += 4) sum += node_row(sidx[j], protEmb)[col];
    redA[t] = sum;
    __syncthreads();
    if (t < 128) {
        float inv = 1.f / fmaxf((float)deg, 1.f);
        s1[t] = (redA[t] + redA[t + 128] + redA[t + 256] + redA[t + 384]) * inv;
        s2[t] = g_xd[v * EMB + t];
    }
    __syncthreads();
    // SAGE GEMV, K split 4 ways
    {
        float a0 = 0.f, a1 = 0.f;
#pragma unroll
        for (int k0 = 0; k0 < 32; k0 += 2) {
            int k = q * 32 + k0;
            a0 += s1[k] * g_Wlt[k * 128 + col] + s2[k] * g_Wrt[k * 128 + col];
            a1 += s1[k + 1] * g_Wlt[(k + 1) * 128 + col] + s2[k + 1] * g_Wrt[(k + 1) * 128 + col];
        }
        redA[t] = a0 + a1;
    }
    __syncthreads();
    if (t < 128)
        sx[t] = fmaxf(redA[t] + redA[t + 128] + redA[t + 256] + redA[t + 384] + bl[t], 0.f);
    __syncthreads();
    // U/V GEMV, K split 4 ways
    {
        float u0 = 0.f, w0 = 0.f;
#pragma unroll
        for (int k0 = 0; k0 < 32; k0++) {
            int k = q * 32 + k0;
            float x = sx[k];
            u0 += x * g_W1pt[k * 128 + col];
            w0 += x * g_W1pt[(128 + k) * 128 + col];
        }
        redA[t] = u0; redB[t] = w0;
    }
    __syncthreads();
    if (t < 128) {
        g_U[v * EMB + t] = redA[t] + redA[t + 128] + redA[t + 256] + redA[t + 384];
        g_V[v * EMB + t] = redB[t] + redB[t + 128] + redB[t + 256] + redB[t + 384];
    }
}

// ================= phase 4: pair MLP + anchor dot, 8 anchors/warp ================
__global__ void k_final(const int* __restrict__ anch, const int* __restrict__ tpl,
                        const float* __restrict__ ob1, const float* __restrict__ oW2,
                        const float* __restrict__ ob2, float* __restrict__ out) {
    int gid = blockIdx.x * 256 + threadIdx.x;   // 128 blocks x 256
    if (gid < ND) g_deg[gid] = 0;               // reset cursor for next call/replay
    int warp = gid >> 5;                        // 0..1023
    int lane = threadIdx.x & 31;
    int base = warp * 8;
    float4 b = ((const float4*)ob1)[lane];
    float dd[8];
    int sr[8];
#pragma unroll
    for (int r = 0; r < 8; r++) {
        int a = anch[base + r];
        int p = a / NSE;                        // constant-div -> mul.hi
        int s = a - p * NSE;
        sr[r] = s;
        int ia = tpl[2 * p], ib = tpl[2 * p + 1];
        float4 u = ((const float4*)g_U)[ia * 32 + lane];
        float4 v = ((const float4*)g_V)[ib * 32 + lane];
        float4 y = ((const float4*)(oW2 + s * EMB))[lane];
        float x0 = fmaxf(u.x + v.x + b.x, 0.f);
        float x1 = fmaxf(u.y + v.y + b.y, 0.f);
        float x2 = fmaxf(u.z + v.z + b.z, 0.f);
        float x3 = fmaxf(u.w + v.w + b.w, 0.f);
        dd[r] = x0 * y.x + x1 * y.y + x2 * y.z + x3 * y.w;
    }
#pragma unroll
    for (int r = 0; r < 8; r++) {
        float d = dd[r];
#pragma unroll
        for (int off = 16; off; off >>= 1) d += __shfl_xor_sync(0xffffffffu, d, off);
        if (lane == 0) out[base + r] = fmaxf(d + ob2[sr[r]], 0.f);
    }
}

// ---------------- launch ----------------
extern "C" void kernel_launch(void* const* d_in, const int* in_sizes, int n_in,
                              void* d_out, int out_size) {
    const int*   ei      = (const int*)d_in[0];
    const float* drugF   = (const float*)d_in[1];
    const int*   tpl     = (const int*)d_in[2];
    const int*   anch    = (const int*)d_in[3];
    const float* W1      = (const float*)d_in[4];
    const float* b1      = (const float*)d_in[5];
    const float* W2      = (const float*)d_in[6];
    const float* b2      = (const float*)d_in[7];
    const float* protEmb = (const float*)d_in[8];
    const float* sageWl  = (const float*)d_in[9];
    const float* sagebl  = (const float*)d_in[10];
    const float* sageWr  = (const float*)d_in[11];
    const float* outW1   = (const float*)d_in[12];
    const float* outb1   = (const float*)d_in[13];
    const float* outW2   = (const float*)d_in[14];
    const float* outb2   = (const float*)d_in[15];
    float* out = (float*)d_out;

    k_phase1<<<P1_GRID, 256>>>(ei, drugF, W1,
                               W2, sageWl + EMB * EMB, sageWr + EMB * EMB, outW1);
    k_mlp12<<<600, 512>>>(b1, b2);
    k_aggsage<<<600, 512>>>(protEmb, sagebl + EMB);
    k_final<<<128, 256>>>(anch, tpl, outb1, outW2, outb2, out);
}

// round 7
// speedup vs baseline: 1.0158x; 1.0158x over previous
#include <cuda_runtime.h>

#define ND 600
#define NPRO 19081
#define NSE 964
#define EMB 128
#define FEAT 2048
#define NE 1200000
#define NPAIRS 8192
#define NANCH 8192
#define NV 19681
#define KSPLIT 32
#define MPAD 640
#define BCAP 160

// phase-1 block-role partition (all 256-thread blocks)
#define EDGE_BLKS 516
#define MLP1_BLKS 608          /* 19 row-tiles x 32 k-splits */
#define INIT_BLKS 320          /* 81920 transpose elements / 256 */
#define P1_GRID (EDGE_BLKS + MLP1_BLKS + INIT_BLKS)

// ---------------- scratch (static device globals; zero-initialized at load) -----
__device__ float g_part[KSPLIT * MPAD * EMB];   // mlp1 split-K partials
__device__ float g_xd[ND * EMB];                // relu MLP output == xF[:600]
__device__ float g_U[ND * EMB];                 // x600 @ Wa^T
__device__ float g_V[ND * EMB];                 // x600 @ Wb^T
__device__ int   g_deg[ND];                     // degree == bucket cursor (zeroed by k_final tail)
__device__ int   g_bkt[ND * BCAP];              // per-node src buckets
__device__ float g_W2t[EMB * EMB];              // W2^T        [k][o]
__device__ float g_Wlt[EMB * EMB];              // sageWl[1]^T [k][o]
__device__ float g_Wrt[EMB * EMB];              // sageWr[1]^T [k][o]
__device__ float g_W1pt[2 * EMB * EMB];         // outW1^T     [k(0..255)][o]

// ================= phase 1: edges scatter + MLP1 split-K GEMM + weight transposes
__global__ void k_phase1(const int* __restrict__ ei,
                         const float* __restrict__ A, const float* __restrict__ W,
                         const float* __restrict__ W2, const float* __restrict__ Wl,
                         const float* __restrict__ Wr, const float* __restrict__ oW1) {
    __shared__ __align__(16) float As[16][32];
    __shared__ __align__(16) float Bs[16][128];
    int b = blockIdx.x;
    int t = threadIdx.x;

    if (b < EDGE_BLKS) {
        const int4* dst4 = (const int4*)(ei + NE);
        int stride = EDGE_BLKS * 256;
        for (int i = b * 256 + t; i < NE / 4; i += stride) {
            int4 d4 = dst4[i];
            int base = i * 4;
            if (d4.x < ND) { int p = atomicAdd(&g_deg[d4.x], 1); g_bkt[d4.x * BCAP + p] = ei[base + 0]; }
            if (d4.y < ND) { int p = atomicAdd(&g_deg[d4.y], 1); g_bkt[d4.y * BCAP + p] = ei[base + 1]; }
            if (d4.z < ND) { int p = atomicAdd(&g_deg[d4.z], 1); g_bkt[d4.z * BCAP + p] = ei[base + 2]; }
            if (d4.w < ND) { int p = atomicAdd(&g_deg[d4.w], 1); g_bkt[d4.w * BCAP + p] = ei[base + 3]; }
        }
        return;
    }
    if (b < EDGE_BLKS + MLP1_BLKS) {
        int b2 = b - EDGE_BLKS;
        int rt = b2 % 19, ks = b2 / 19;
        int tx = t & 31, ty = t >> 5;
        int rowBase = rt * 32;
        int kbase = ks * 64;
        float acc[4][4];
#pragma unroll
        for (int i = 0; i < 4; i++)
#pragma unroll
            for (int j = 0; j < 4; j++) acc[i][j] = 0.f;

        for (int kk = 0; kk < 4; kk++) {
            if (t < 128) {
                int r = t >> 2, c4 = t & 3;
                int row = rowBase + r;
                float4 va = make_float4(0.f, 0.f, 0.f, 0.f);
                if (row < ND) va = *(const float4*)(A + row * FEAT + kbase + kk * 16 + c4 * 4);
                As[c4 * 4 + 0][r] = va.x; As[c4 * 4 + 1][r] = va.y;
                As[c4 * 4 + 2][r] = va.z; As[c4 * 4 + 3][r] = va.w;
            }
#pragma unroll
            for (int q = 0; q < 2; q++) {
                int idx = t + q * 256;
                int wr = idx >> 2, wc = idx & 3;
                float4 vb = *(const float4*)(W + wr * FEAT + kbase + kk * 16 + wc * 4);
                Bs[wc * 4 + 0][wr] = vb.x; Bs[wc * 4 + 1][wr] = vb.y;
                Bs[wc * 4 + 2][wr] = vb.z; Bs[wc * 4 + 3][wr] = vb.w;
            }
            __syncthreads();
#pragma unroll
            for (int k = 0; k < 16; k++) {
                float a[4], bb[4];
                *(float4*)(a)  = *(const float4*)&As[k][ty * 4];
                *(float4*)(bb) = *(const float4*)&Bs[k][tx * 4];
#pragma unroll
                for (int i = 0; i < 4; i++)
#pragma unroll
                    for (int j = 0; j < 4; j++) acc[i][j] += a[i] * bb[j];
            }
            __syncthreads();
        }
        float* out = g_part + ks * (MPAD * EMB) + rowBase * EMB;
#pragma unroll
        for (int i = 0; i < 4; i++) {
            float4 v = make_float4(acc[i][0], acc[i][1], acc[i][2], acc[i][3]);
            *(float4*)(out + (ty * 4 + i) * EMB + tx * 4) = v;
        }
        return;
    }
    int idx = (b - EDGE_BLKS - MLP1_BLKS) * 256 + t;       // [0, 81920)
    if (idx < 16384) {
        int k = idx >> 7, o = idx & 127;
        g_W2t[idx] = W2[o * 128 + k];
    } else if (idx < 32768) {
        int f = idx - 16384; int k = f >> 7, o = f & 127;
        g_Wlt[f] = Wl[o * 128 + k];
    } else if (idx < 49152) {
        int f = idx - 32768; int k = f >> 7, o = f & 127;
        g_Wrt[f] = Wr[o * 128 + k];
    } else {
        int f = idx - 49152; int k = f >> 7, o = f & 127;   // k in [0,256)
        g_W1pt[f] = oW1[o * 256 + k];
    }
}

// ================= phase 2: split-K reduce + bias + relu + MLP2 (600 x 512) ======
__global__ void k_mlp12(const float* __restrict__ b1, const float* __restrict__ b2) {
    int row = blockIdx.x;
    int t = threadIdx.x;            // 512
    int col = t & 127, q = t >> 7;  // q in [0,4)
    __shared__ float red[512];
    __shared__ float hs[128];
    float s = 0.f;
    const float* p = g_part + row * EMB + col;
#pragma unroll
    for (int i = 0; i < 8; i++) s += p[(q * 8 + i) * (MPAD * EMB)];
    red[t] = s;
    __syncthreads();
    if (t < 128) {
        float h = red[t] + red[t + 128] + red[t + 256] + red[t + 384] + b1[t];
        hs[t] = fmaxf(h, 0.f);
    }
    __syncthreads();
    float a0 = 0.f, a1 = 0.f;
#pragma unroll
    for (int k = 0; k < 32; k += 2) {
        int kk = q * 32 + k;
        a0 += hs[kk] * g_W2t[kk * 128 + col];
        a1 += hs[kk + 1] * g_W2t[(kk + 1) * 128 + col];
    }
    red[t] = a0 + a1;
    __syncthreads();
    if (t < 128) {
        float r = red[t] + red[t + 128] + red[t + 256] + red[t + 384] + b2[t];
        g_xd[row * EMB + t] = fmaxf(r, 0.f);
    }
}

// ================= phase 3: aggregation + SAGE + U/V (600 x 512, 4-way split) ====
__device__ __forceinline__ const float* node_row(int s, const float* protEmb) {
    return (s < ND) ? g_xd + s * EMB : protEmb + (s - ND) * EMB;
}

__global__ void k_aggsage(const float* __restrict__ protEmb, const float* __restrict__ bl) {
    int v = blockIdx.x;
    int t = threadIdx.x;            // 512
    int col = t & 127, q = t >> 7;  // q in [0,4)
    __shared__ float redA[512], redB[512];
    __shared__ float s1[128], s2[128], sx[128];
    __shared__ int sidx[BCAP];
    int deg = g_deg[v];
    if (t < deg) sidx[t] = g_bkt[v * BCAP + t];     // deg <= BCAP < 512
    __syncthreads();
    // group q sums neighbors j = q, q+4, q+8, ... (coalesced 512B row reads)
    float sum = 0.f;
    int j = q;
    for (; j + 12 < deg; j += 16) {
        const float* p0 = node_row(sidx[j],      protEmb);
        const float* p1 = node_row(sidx[j + 4],  protEmb);
        const float* p2 = node_row(sidx[j + 8],  protEmb);
        const float* p3 = node_row(sidx[j + 12], protEmb);
        sum += (p0[col] + p1[col]) + (p2[col] + p3[col]);
    }
    for (; j < deg; j += 4) sum += node_row(sidx[j], protEmb)[col];
    redA[t] = sum;
    __syncthreads();
    if (t < 128) {
        float inv = 1.f / fmaxf((float)deg, 1.f);
        s1[t] = (redA[t] + redA[t + 128] + redA[t + 256] + redA[t + 384]) * inv;
        s2[t] = g_xd[v * EMB + t];
    }
    __syncthreads();
    // SAGE GEMV, K split 4 ways
    {
        float a0 = 0.f, a1 = 0.f;
#pragma unroll
        for (int k0 = 0; k0 < 32; k0 += 2) {
            int k = q * 32 + k0;
            a0 += s1[k] * g_Wlt[k * 128 + col] + s2[k] * g_Wrt[k * 128 + col];
            a1 += s1[k + 1] * g_Wlt[(k + 1) * 128 + col] + s2[k + 1] * g_Wrt[(k + 1) * 128 + col];
        }
        redA[t] = a0 + a1;
    }
    __syncthreads();
    if (t < 128)
        sx[t] = fmaxf(redA[t] + redA[t + 128] + redA[t + 256] + redA[t + 384] + bl[t], 0.f);
    __syncthreads();
    // U/V GEMV, K split 4 ways
    {
        float u0 = 0.f, w0 = 0.f;
#pragma unroll
        for (int k0 = 0; k0 < 32; k0++) {
            int k = q * 32 + k0;
            float x = sx[k];
            u0 += x * g_W1pt[k * 128 + col];
            w0 += x * g_W1pt[(128 + k) * 128 + col];
        }
        redA[t] = u0; redB[t] = w0;
    }
    __syncthreads();
    if (t < 128) {
        g_U[v * EMB + t] = redA[t] + redA[t + 128] + redA[t + 256] + redA[t + 384];
        g_V[v * EMB + t] = redB[t] + redB[t + 128] + redB[t + 256] + redB[t + 384];
    }
}

// ================= phase 4: pair MLP + anchor dot, 4 anchors/warp, 2048 warps ====
__global__ void k_final(const int* __restrict__ anch, const int* __restrict__ tpl,
                        const float* __restrict__ ob1, const float* __restrict__ oW2,
                        const float* __restrict__ ob2, float* __restrict__ out) {
    int gid = blockIdx.x * 256 + threadIdx.x;   // 256 blocks x 256
    if (gid < ND) g_deg[gid] = 0;               // reset cursor for next call/replay
    int warp = gid >> 5;                        // 0..2047
    int lane = threadIdx.x & 31;
    int base = warp * 4;
    float4 b = ((const float4*)ob1)[lane];
    float dd[4];
    int sr[4];
#pragma unroll
    for (int r = 0; r < 4; r++) {
        int a = anch[base + r];
        int p = a / NSE;                        // constant-div -> mul.hi
        int s = a - p * NSE;
        sr[r] = s;
        int ia = tpl[2 * p], ib = tpl[2 * p + 1];
        float4 u = ((const float4*)g_U)[ia * 32 + lane];
        float4 v = ((const float4*)g_V)[ib * 32 + lane];
        float4 y = ((const float4*)(oW2 + s * EMB))[lane];
        float x0 = fmaxf(u.x + v.x + b.x, 0.f);
        float x1 = fmaxf(u.y + v.y + b.y, 0.f);
        float x2 = fmaxf(u.z + v.z + b.z, 0.f);
        float x3 = fmaxf(u.w + v.w + b.w, 0.f);
        dd[r] = x0 * y.x + x1 * y.y + x2 * y.z + x3 * y.w;
    }
#pragma unroll
    for (int r = 0; r < 4; r++) {
        float d = dd[r];
#pragma unroll
        for (int off = 16; off; off >>= 1) d += __shfl_xor_sync(0xffffffffu, d, off);
        if (lane == 0) out[base + r] = fmaxf(d + ob2[sr[r]], 0.f);
    }
}

// ---------------- launch ----------------
extern "C" void kernel_launch(void* const* d_in, const int* in_sizes, int n_in,
                              void* d_out, int out_size) {
    const int*   ei      = (const int*)d_in[0];
    const float* drugF   = (const float*)d_in[1];
    const int*   tpl     = (const int*)d_in[2];
    const int*   anch    = (const int*)d_in[3];
    const float* W1      = (const float*)d_in[4];
    const float* b1      = (const float*)d_in[5];
    const float* W2      = (const float*)d_in[6];
    const float* b2      = (const float*)d_in[7];
    const float* protEmb = (const float*)d_in[8];
    const float* sageWl  = (const float*)d_in[9];
    const float* sagebl  = (const float*)d_in[10];
    const float* sageWr  = (const float*)d_in[11];
    const float* outW1   = (const float*)d_in[12];
    const float* outb1   = (const float*)d_in[13];
    const float* outW2   = (const float*)d_in[14];
    const float* outb2   = (const float*)d_in[15];
    float* out = (float*)d_out;

    k_phase1<<<P1_GRID, 256>>>(ei, drugF, W1,
                               W2, sageWl + EMB * EMB, sageWr + EMB * EMB, outW1);
    k_mlp12<<<600, 512>>>(b1, b2);
    k_aggsage<<<600, 512>>>(protEmb, sagebl + EMB);
    k_final<<<256, 256>>>(anch, tpl, outb1, outW2, outb2, out);
}

// round 9
// speedup vs baseline: 1.0355x; 1.0194x over previous
#include <cuda_runtime.h>

#define ND 600
#define NPRO 19081
#define NSE 964
#define EMB 128
#define FEAT 2048
#define NE 1200000
#define NPAIRS 8192
#define NANCH 8192
#define NV 19681
#define KSPLIT 32
#define MPAD 640
#define BCAP 160

// phase-1 block-role partition (all 256-thread blocks)
#define EDGE_BLKS 516
#define MLP1_BLKS 608          /* 19 row-tiles x 32 k-splits */
#define INIT_BLKS 320          /* 81920 transpose elements / 256 */
#define ANCH_BLKS 32           /* 8192 anchors / 256 */
#define P1_GRID (EDGE_BLKS + MLP1_BLKS + INIT_BLKS + ANCH_BLKS)

// ---------------- scratch (static device globals; zero-initialized at load) -----
__device__ float g_part[KSPLIT * MPAD * EMB];   // mlp1 split-K partials
__device__ float g_xd[ND * EMB];                // relu MLP output == xF[:600]
__device__ float g_U[ND * EMB];                 // x600 @ Wa^T
__device__ float g_V[ND * EMB];                 // x600 @ Wb^T
__device__ int   g_deg[ND];                     // degree == bucket cursor (zeroed by k_final tail)
__device__ int   g_bkt[ND * BCAP];              // per-node src buckets
__device__ int4  g_pairs[NANCH];                // pre-decoded (ia, ib, s, 0) per anchor
__device__ float g_W2t[EMB * EMB];              // W2^T        [k][o]
__device__ float g_Wlt[EMB * EMB];              // sageWl[1]^T [k][o]
__device__ float g_Wrt[EMB * EMB];              // sageWr[1]^T [k][o]
__device__ float g_W1pt[2 * EMB * EMB];         // outW1^T     [k(0..255)][o]

// ================= phase 1: edges + MLP1 GEMM + transposes + anchor decode =======
__global__ void k_phase1(const int* __restrict__ ei,
                         const float* __restrict__ A, const float* __restrict__ W,
                         const float* __restrict__ W2, const float* __restrict__ Wl,
                         const float* __restrict__ Wr, const float* __restrict__ oW1,
                         const int* __restrict__ anch, const int* __restrict__ tpl) {
    __shared__ __align__(16) float As[16][32];
    __shared__ __align__(16) float Bs[16][128];
    int b = blockIdx.x;
    int t = threadIdx.x;

    if (b < EDGE_BLKS) {
        const int4* dst4 = (const int4*)(ei + NE);
        int stride = EDGE_BLKS * 256;
        for (int i = b * 256 + t; i < NE / 4; i += stride) {
            int4 d4 = dst4[i];
            int base = i * 4;
            if (d4.x < ND) { int p = atomicAdd(&g_deg[d4.x], 1); g_bkt[d4.x * BCAP + p] = ei[base + 0]; }
            if (d4.y < ND) { int p = atomicAdd(&g_deg[d4.y], 1); g_bkt[d4.y * BCAP + p] = ei[base + 1]; }
            if (d4.z < ND) { int p = atomicAdd(&g_deg[d4.z], 1); g_bkt[d4.z * BCAP + p] = ei[base + 2]; }
            if (d4.w < ND) { int p = atomicAdd(&g_deg[d4.w], 1); g_bkt[d4.w * BCAP + p] = ei[base + 3]; }
        }
        return;
    }
    if (b < EDGE_BLKS + MLP1_BLKS) {
        int b2 = b - EDGE_BLKS;
        int rt = b2 % 19, ks = b2 / 19;
        int tx = t & 31, ty = t >> 5;
        int rowBase = rt * 32;
        int kbase = ks * 64;
        float acc[4][4];
#pragma unroll
        for (int i = 0; i < 4; i++)
#pragma unroll
            for (int j = 0; j < 4; j++) acc[i][j] = 0.f;

        for (int kk = 0; kk < 4; kk++) {
            if (t < 128) {
                int r = t >> 2, c4 = t & 3;
                int row = rowBase + r;
                float4 va = make_float4(0.f, 0.f, 0.f, 0.f);
                if (row < ND) va = *(const float4*)(A + row * FEAT + kbase + kk * 16 + c4 * 4);
                As[c4 * 4 + 0][r] = va.x; As[c4 * 4 + 1][r] = va.y;
                As[c4 * 4 + 2][r] = va.z; As[c4 * 4 + 3][r] = va.w;
            }
#pragma unroll
            for (int q = 0; q < 2; q++) {
                int idx = t + q * 256;
                int wr = idx >> 2, wc = idx & 3;
                float4 vb = *(const float4*)(W + wr * FEAT + kbase + kk * 16 + wc * 4);
                Bs[wc * 4 + 0][wr] = vb.x; Bs[wc * 4 + 1][wr] = vb.y;
                Bs[wc * 4 + 2][wr] = vb.z; Bs[wc * 4 + 3][wr] = vb.w;
            }
            __syncthreads();
#pragma unroll
            for (int k = 0; k < 16; k++) {
                float a[4], bb[4];
                *(float4*)(a)  = *(const float4*)&As[k][ty * 4];
                *(float4*)(bb) = *(const float4*)&Bs[k][tx * 4];
#pragma unroll
                for (int i = 0; i < 4; i++)
#pragma unroll
                    for (int j = 0; j < 4; j++) acc[i][j] += a[i] * bb[j];
            }
            __syncthreads();
        }
        float* out = g_part + ks * (MPAD * EMB) + rowBase * EMB;
#pragma unroll
        for (int i = 0; i < 4; i++) {
            float4 v = make_float4(acc[i][0], acc[i][1], acc[i][2], acc[i][3]);
            *(float4*)(out + (ty * 4 + i) * EMB + tx * 4) = v;
        }
        return;
    }
    if (b < EDGE_BLKS + MLP1_BLKS + INIT_BLKS) {
        int idx = (b - EDGE_BLKS - MLP1_BLKS) * 256 + t;       // [0, 81920)
        if (idx < 16384) {
            int k = idx >> 7, o = idx & 127;
            g_W2t[idx] = W2[o * 128 + k];
        } else if (idx < 32768) {
            int f = idx - 16384; int k = f >> 7, o = f & 127;
            g_Wlt[f] = Wl[o * 128 + k];
        } else if (idx < 49152) {
            int f = idx - 32768; int k = f >> 7, o = f & 127;
            g_Wrt[f] = Wr[o * 128 + k];
        } else {
            int f = idx - 49152; int k = f >> 7, o = f & 127;   // k in [0,256)
            g_W1pt[f] = oW1[o * 256 + k];
        }
        return;
    }
    // ---- anchor decode role: (ia, ib, s) per anchor ----
    {
        int i = (b - EDGE_BLKS - MLP1_BLKS - INIT_BLKS) * 256 + t;   // [0, 8192)
        int a = anch[i];
        int p = a / NSE;                   // constant-div -> mul.hi
        int s = a - p * NSE;
        g_pairs[i] = make_int4(tpl[2 * p], tpl[2 * p + 1], s, 0);
    }
}

// ================= phase 2: split-K reduce + bias + relu + MLP2 (600 x 512) ======
__global__ void k_mlp12(const float* __restrict__ b1, const float* __restrict__ b2) {
    int row = blockIdx.x;
    int t = threadIdx.x;            // 512
    int col = t & 127, q = t >> 7;  // q in [0,4)
    __shared__ float red[512];
    __shared__ float hs[128];
    float s = 0.f;
    const float* p = g_part + row * EMB + col;
#pragma unroll
    for (int i = 0; i < 8; i++) s += p[(q * 8 + i) * (MPAD * EMB)];
    red[t] = s;
    __syncthreads();
    if (t < 128) {
        float h = red[t] + red[t + 128] + red[t + 256] + red[t + 384] + b1[t];
        hs[t] = fmaxf(h, 0.f);
    }
    __syncthreads();
    float a0 = 0.f, a1 = 0.f;
#pragma unroll
    for (int k = 0; k < 32; k += 2) {
        int kk = q * 32 + k;
        a0 += hs[kk] * g_W2t[kk * 128 + col];
        a1 += hs[kk + 1] * g_W2t[(kk + 1) * 128 + col];
    }
    red[t] = a0 + a1;
    __syncthreads();
    if (t < 128) {
        float r = red[t] + red[t + 128] + red[t + 256] + red[t + 384] + b2[t];
        g_xd[row * EMB + t] = fmaxf(r, 0.f);
    }
}

// ================= phase 3: aggregation + SAGE + U/V (600 x 512, 4-way split) ====
__device__ __forceinline__ const float* node_row(int s, const float* protEmb) {
    return (s < ND) ? g_xd + s * EMB : protEmb + (s - ND) * EMB;
}

__global__ void k_aggsage(const float* __restrict__ protEmb, const float* __restrict__ bl) {
    int v = blockIdx.x;
    int t = threadIdx.x;            // 512
    int col = t & 127, q = t >> 7;  // q in [0,4)
    __shared__ float redA[512], redB[512];
    __shared__ float s1[128], s2[128], sx[128];
    __shared__ int sidx[BCAP];
    int deg = g_deg[v];
    if (t < deg) sidx[t] = g_bkt[v * BCAP + t];     // deg <= BCAP < 512
    __syncthreads();
    // group q sums neighbors j = q, q+4, q+8, ... (coalesced 512B row reads)
    float sum = 0.f;
    int j = q;
    for (; j + 12 < deg; j += 16) {
        const float* p0 = node_row(sidx[j],      protEmb);
        const float* p1 = node_row(sidx[j + 4],  protEmb);
        const float* p2 = node_row(sidx[j + 8],  protEmb);
        const float* p3 = node_row(sidx[j + 12], protEmb);
        sum += (p0[col] + p1[col]) + (p2[col] + p3[col]);
    }
    for (; j < deg; j += 4) sum += node_row(sidx[j], protEmb)[col];
    redA[t] = sum;
    __syncthreads();
    if (t < 128) {
        float inv = 1.f / fmaxf((float)deg, 1.f);
        s1[t] = (redA[t] + redA[t + 128] + redA[t + 256] + redA[t + 384]) * inv;
        s2[t] = g_xd[v * EMB + t];
    }
    __syncthreads();
    // SAGE GEMV, K split 4 ways
    {
        float a0 = 0.f, a1 = 0.f;
#pragma unroll
        for (int k0 = 0; k0 < 32; k0 += 2) {
            int k = q * 32 + k0;
            a0 += s1[k] * g_Wlt[k * 128 + col] + s2[k] * g_Wrt[k * 128 + col];
            a1 += s1[k + 1] * g_Wlt[(k + 1) * 128 + col] + s2[k + 1] * g_Wrt[(k + 1) * 128 + col];
        }
        redA[t] = a0 + a1;
    }
    __syncthreads();
    if (t < 128)
        sx[t] = fmaxf(redA[t] + redA[t + 128] + redA[t + 256] + redA[t + 384] + bl[t], 0.f);
    __syncthreads();
    // U/V GEMV, K split 4 ways
    {
        float u0 = 0.f, w0 = 0.f;
#pragma unroll
        for (int k0 = 0; k0 < 32; k0++) {
            int k = q * 32 + k0;
            float x = sx[k];
            u0 += x * g_W1pt[k * 128 + col];
            w0 += x * g_W1pt[(128 + k) * 128 + col];
        }
        redA[t] = u0; redB[t] = w0;
    }
    __syncthreads();
    if (t < 128) {
        g_U[v * EMB + t] = redA[t] + redA[t + 128] + redA[t + 256] + redA[t + 384];
        g_V[v * EMB + t] = redB[t] + redB[t + 128] + redB[t + 256] + redB[t + 384];
    }
}

// ================= phase 4: pair MLP + anchor dot, 1 anchor/warp, 8192 warps =====
__global__ void k_final(const float* __restrict__ ob1, const float* __restrict__ oW2,
                        const float* __restrict__ ob2, float* __restrict__ out) {
    int gid = blockIdx.x * 256 + threadIdx.x;   // 1024 blocks x 256
    if (gid < ND) g_deg[gid] = 0;               // reset cursor for next call/replay
    int w = gid >> 5;                           // 0..8191
    int lane = threadIdx.x & 31;
    int4 pr = g_pairs[w];                       // (ia, ib, s, 0) — broadcast load
    float4 u = ((const float4*)g_U)[pr.x * 32 + lane];
    float4 v = ((const float4*)g_V)[pr.y * 32 + lane];
    float4 y = ((const float4*)(oW2 + pr.z * EMB))[lane];
    float4 b = ((const float4*)ob1)[lane];
    float x0 = fmaxf(u.x + v.x + b.x, 0.f);
    float x1 = fmaxf(u.y + v.y + b.y, 0.f);
    float x2 = fmaxf(u.z + v.z + b.z, 0.f);
    float x3 = fmaxf(u.w + v.w + b.w, 0.f);
    float d = x0 * y.x + x1 * y.y + x2 * y.z + x3 * y.w;
#pragma unroll
    for (int off = 16; off; off >>= 1) d += __shfl_xor_sync(0xffffffffu, d, off);
    if (lane == 0) out[w] = fmaxf(d + ob2[pr.z], 0.f);
}

// ---------------- launch ----------------
extern "C" void kernel_launch(void* const* d_in, const int* in_sizes, int n_in,
                              void* d_out, int out_size) {
    const int*   ei      = (const int*)d_in[0];
    const float* drugF   = (const float*)d_in[1];
    const int*   tpl     = (const int*)d_in[2];
    const int*   anch    = (const int*)d_in[3];
    const float* W1      = (const float*)d_in[4];
    const float* b1      = (const float*)d_in[5];
    const float* W2      = (const float*)d_in[6];
    const float* b2      = (const float*)d_in[7];
    const float* protEmb = (const float*)d_in[8];
    const float* sageWl  = (const float*)d_in[9];
    const float* sagebl  = (const float*)d_in[10];
    const float* sageWr  = (const float*)d_in[11];
    const float* outW1   = (const float*)d_in[12];
    const float* outb1   = (const float*)d_in[13];
    const float* outW2   = (const float*)d_in[14];
    const float* outb2   = (const float*)d_in[15];
    float* out = (float*)d_out;

    k_phase1<<<P1_GRID, 256>>>(ei, drugF, W1,
                               W2, sageWl + EMB * EMB, sageWr + EMB * EMB, outW1,
                               anch, tpl);
    k_mlp12<<<600, 512>>>(b1, b2);
    k_aggsage<<<600, 512>>>(protEmb, sagebl + EMB);
    k_final<<<1024, 256>>>(outb1, outW2, outb2, out);
}